// round 10
// baseline (speedup 1.0000x reference)
#include <cuda_runtime.h>

// Problem constants (fixed by the dataset)
#define BB   256
#define NN   32
#define WW   1920
#define HH   1080
#define ROWS (BB * NN)          // 8192
#define GRID (2 * ROWS)         // 16384: [0,ROWS) = x-rows, [ROWS,2*ROWS) = y-rows
#define NSLOTS 32

// Scratch (alloc-free rule: __device__ globals; zero-initialized at module load,
// and the last block of every launch resets them, so graph replays are deterministic)
__device__ float        g_accs[NSLOTS];
__device__ float        g_counts[NSLOTS];
__device__ unsigned int g_done;

__inline__ __device__ float warp_sum(float v) {
    #pragma unroll
    for (int o = 16; o > 0; o >>= 1)
        v += __shfl_xor_sync(0xffffffffu, v, o);
    return v;
}

// Single fused kernel:
//   block bid < ROWS      : pred_x row r=bid      (1920 f32) + gather terms + count
//   block bid >= ROWS     : pred_y row r=bid-ROWS (1080 f32) + gather term
// Each block recomputes its row's mask from tgt (16B, L2-hot) -> no inter-kernel dep.
// Per-block partial goes to g_accs[bid & 31] (striped to kill atomic serialization).
// The last block to finish (ticket on g_done) reduces the slots, writes out,
// and resets all scratch.
__global__ void __launch_bounds__(256, 8)
hbdl_fused_kernel(const float* __restrict__ px,
                  const float* __restrict__ py,
                  const long long* __restrict__ tgt,
                  float* __restrict__ out) {
    const int bid  = blockIdx.x;
    const int tid  = threadIdx.x;
    const bool is_x = (bid < ROWS);
    const int r    = is_x ? bid : bid - ROWS;

    // --- recompute mask/target for this row (cheap, L2-resident) ---
    longlong2 t2 = ((const longlong2*)tgt)[r];
    int tx = min(max((int)t2.x, 0), WW - 1);
    int ty = min(max((int)t2.y, 0), HH - 1);
    float m = ((tx == 0) && (ty == 0)) ? 0.0f : 1.0f;

    float contrib = 0.0f;   // this block's contribution to the global sum (thread-local)

    if (m != 0.0f) {
        const float4* ptr;
        int n4, t_idx;
        float inv_l;
        if (is_x) {
            ptr   = (const float4*)(px + (size_t)r * WW);
            n4    = WW / 4;               // 480
            inv_l = 1.0f / (float)WW;
            t_idx = tx;
        } else {
            ptr   = (const float4*)(py + (size_t)r * HH);
            n4    = HH / 4;               // 270
            inv_l = 1.0f / (float)HH;
            t_idx = ty;
        }

        // Streaming: -sum_i clamp(log(1-p_i)) / L
        float s = 0.0f;
        for (int i = tid; i < n4; i += blockDim.x) {
            float4 v = ptr[i];
            s += fmaxf(__logf(1.0f - v.x), -100.0f);
            s += fmaxf(__logf(1.0f - v.y), -100.0f);
            s += fmaxf(__logf(1.0f - v.z), -100.0f);
            s += fmaxf(__logf(1.0f - v.w), -100.0f);
        }
        contrib = -s * inv_l;

        // Gather term: (+clamp(log1p(1-p_t)) - clamp(log(p_t))) / L  (thread 0 only)
        if (tid == 0) {
            float p   = ((const float*)ptr)[t_idx];
            float lp  = fmaxf(__logf(p),        -100.0f);
            float l1p = fmaxf(__logf(1.0f - p), -100.0f);
            contrib += (l1p - lp) * inv_l;
        }
    }

    // --- block reduce ---
    __shared__ float sh[8];
    int lane = tid & 31;
    int wid  = tid >> 5;
    float bsum = warp_sum(contrib);
    if (lane == 0) sh[wid] = bsum;
    __syncthreads();
    if (tid == 0) {
        float t = 0.0f;
        #pragma unroll
        for (int w = 0; w < 8; w++) t += sh[w];
        if (t != 0.0f) atomicAdd(&g_accs[bid & (NSLOTS - 1)], t);
        if (is_x && m != 0.0f) atomicAdd(&g_counts[bid & (NSLOTS - 1)], m);
    }

    // --- last-block finalize + scratch reset (deterministic graph replays) ---
    __shared__ bool isLast;
    if (tid == 0) {
        __threadfence();
        unsigned int ticket = atomicAdd(&g_done, 1u);
        isLast = (ticket == (unsigned int)(GRID - 1));
    }
    __syncthreads();
    if (isLast) {
        if (tid < NSLOTS) {
            volatile float* va = g_accs;
            volatile float* vc = g_counts;
            float a = va[tid];
            float c = vc[tid];
            a = warp_sum(a);
            c = warp_sum(c);
            if (tid == 0) out[0] = a / fmaxf(c, 1.0f);
            // reset scratch for the next replay
            g_accs[tid]   = 0.0f;
            g_counts[tid] = 0.0f;
        }
        if (tid == 0) g_done = 0u;
    }
}

extern "C" void kernel_launch(void* const* d_in, const int* in_sizes, int n_in,
                              void* d_out, int out_size) {
    const float*     px  = (const float*)d_in[0];       // [256,32,1920] f32
    const float*     py  = (const float*)d_in[1];       // [256,32,1080] f32
    const long long* tgt = (const long long*)d_in[2];   // [256,32,2] i64
    float* out = (float*)d_out;

    hbdl_fused_kernel<<<GRID, 256>>>(px, py, tgt, out);
}